// round 1
// baseline (speedup 1.0000x reference)
#include <cuda_runtime.h>
#include <cstdint>

// Problem constants: input [32, 512, 512, 3] float32, NHWC, 3x3 median, replicate border.
constexpr int Bn  = 32;
constexpr int H   = 512;
constexpr int W   = 512;
constexpr int C   = 3;
constexpr int ROW = W * C;          // 1536 floats per image row
constexpr int IMG = H * ROW;        // floats per image
constexpr int EPT = 8;              // elements (wc) per thread
constexpr int TPR = ROW / EPT;      // 192 threads per image row
constexpr int NTHREADS = Bn * H * TPR;   // 3,145,728
constexpr int BLOCK = 256;

// --- min/max helpers (all compile to FMNMX on the alu pipe) ---
__device__ __forceinline__ float med3f(float a, float b, float c) {
    // median of 3: max(min(a,b), min(max(a,b), c))  -> 4 ops
    float mn = fminf(a, b);
    float mx = fmaxf(a, b);
    return fmaxf(mn, fminf(mx, c));
}
__device__ __forceinline__ float max3f(float a, float b, float c) {
    return fmaxf(fmaxf(a, b), c);
}
__device__ __forceinline__ float min3f(float a, float b, float c) {
    return fminf(fminf(a, b), c);
}
// full sort of a vertical column triple -> (mn, md, mx), 6 ops
__device__ __forceinline__ void sort3f(float a, float b, float c,
                                       float& mn, float& md, float& mx) {
    float lo = fminf(a, b);
    float hi = fmaxf(a, b);
    mn = fminf(lo, c);
    mx = fmaxf(hi, c);
    md = fmaxf(lo, fminf(hi, c));
}
// combine three sorted columns into the 3x3 median (classical identity), 12 ops
__device__ __forceinline__ float median9_from_cols(
    float mn0, float md0, float mx0,
    float mn1, float md1, float mx1,
    float mn2, float md2, float mx2) {
    float lo = max3f(mn0, mn1, mn2);
    float mi = med3f(md0, md1, md2);
    float hi = min3f(mx0, mx1, mx2);
    return med3f(lo, mi, hi);
}

__global__ void __launch_bounds__(BLOCK)
median3x3_kernel(const float* __restrict__ in, float* __restrict__ out) {
    int tid = blockIdx.x * BLOCK + threadIdx.x;
    // tid -> (b, h, wc0)
    int wc0 = (tid % TPR) * EPT;
    int hb  = tid / TPR;
    int h   = hb % H;
    int b   = hb / H;

    const float* img = in + (int64_t)b * IMG;
    const float* r0 = img + (int64_t)max(h - 1, 0)     * ROW;   // row above (clamped)
    const float* r1 = img + (int64_t)h                 * ROW;   // center row
    const float* r2 = img + (int64_t)min(h + 1, H - 1) * ROW;   // row below (clamped)

    float* o = out + (int64_t)b * IMG + (int64_t)h * ROW + wc0;

    if (wc0 != 0 && wc0 != ROW - EPT) {
        // ---------- fast interior path ----------
        // window of 16 floats per row: [wc0-4, wc0+12), 16B-aligned
        float a[16], bb[16], cc[16];
        const float4* pa = reinterpret_cast<const float4*>(r0 + wc0 - 4);
        const float4* pb = reinterpret_cast<const float4*>(r1 + wc0 - 4);
        const float4* pc = reinterpret_cast<const float4*>(r2 + wc0 - 4);
        #pragma unroll
        for (int j = 0; j < 4; j++) {
            float4 va = pa[j];
            float4 vb = pb[j];
            float4 vc = pc[j];
            a[4*j+0] = va.x; a[4*j+1] = va.y; a[4*j+2] = va.z; a[4*j+3] = va.w;
            bb[4*j+0] = vb.x; bb[4*j+1] = vb.y; bb[4*j+2] = vb.z; bb[4*j+3] = vb.w;
            cc[4*j+0] = vc.x; cc[4*j+1] = vc.y; cc[4*j+2] = vc.z; cc[4*j+3] = vc.w;
        }
        // sort the 14 vertical columns we need (window idx 1..14 == wc0-3 .. wc0+10)
        float mn[15], md[15], mx[15];
        #pragma unroll
        for (int k = 1; k <= 14; k++) {
            sort3f(a[k], bb[k], cc[k], mn[k], md[k], mx[k]);
        }
        // 8 outputs; output o uses columns (o+1, o+4, o+7) in window coords
        float res[EPT];
        #pragma unroll
        for (int j = 0; j < EPT; j++) {
            int kl = j + 1, kc = j + 4, kr = j + 7;
            res[j] = median9_from_cols(mn[kl], md[kl], mx[kl],
                                       mn[kc], md[kc], mx[kc],
                                       mn[kr], md[kr], mx[kr]);
        }
        float4* po = reinterpret_cast<float4*>(o);
        po[0] = make_float4(res[0], res[1], res[2], res[3]);
        po[1] = make_float4(res[4], res[5], res[6], res[7]);
    } else {
        // ---------- slow edge path (first/last thread of each row) ----------
        float res[EPT];
        #pragma unroll
        for (int j = 0; j < EPT; j++) {
            int wc = wc0 + j;
            int w  = wc / C;
            int c  = wc - w * C;
            int wl = max(w - 1, 0) * C + c;
            int wcc = w * C + c;
            int wr = min(w + 1, W - 1) * C + c;
            float mn0, md0, mx0, mn1, md1, mx1, mn2, md2, mx2;
            sort3f(r0[wl],  r1[wl],  r2[wl],  mn0, md0, mx0);
            sort3f(r0[wcc], r1[wcc], r2[wcc], mn1, md1, mx1);
            sort3f(r0[wr],  r1[wr],  r2[wr],  mn2, md2, mx2);
            res[j] = median9_from_cols(mn0, md0, mx0, mn1, md1, mx1, mn2, md2, mx2);
        }
        float4* po = reinterpret_cast<float4*>(o);
        po[0] = make_float4(res[0], res[1], res[2], res[3]);
        po[1] = make_float4(res[4], res[5], res[6], res[7]);
    }
}

extern "C" void kernel_launch(void* const* d_in, const int* in_sizes, int n_in,
                              void* d_out, int out_size) {
    const float* in = (const float*)d_in[0];
    float* out = (float*)d_out;
    int blocks = NTHREADS / BLOCK;   // 12288
    median3x3_kernel<<<blocks, BLOCK>>>(in, out);
}

// round 2
// speedup vs baseline: 1.4351x; 1.4351x over previous
#include <cuda_runtime.h>
#include <cuda_fp16.h>
#include <cstdint>

// Input [32, 512, 512, 3] float32 NHWC, 3x3 median, replicate border.
constexpr int Bn  = 32;
constexpr int H   = 512;
constexpr int W   = 512;
constexpr int C   = 3;
constexpr int ROW = W * C;            // 1536 floats per image row
constexpr int IMG = H * ROW;
constexpr int EPT = 8;                // wc positions per thread
constexpr int TPR = ROW / EPT;        // 192 threads per row-pair
constexpr int PAIRS = H / 2;          // 256 row pairs per image
constexpr int NTHREADS = Bn * PAIRS * TPR;   // 1,572,864
constexpr int BLOCK = 256;

// Convert a vertical 4-row column into per-lane sorted triples.
// low lane = output row h  (inputs rows h-1, h, h+1)
// high lane = output row h+1 (inputs rows h, h+1, h+2)
// The f32->f16x2 conversion doubles as the lane pack (1 F2FP op each).
__device__ __forceinline__ void col_sort(float a, float b, float c, float d,
                                         __half2& mn, __half2& md, __half2& mx) {
    __half2 x = __floats2half2_rn(a, b);   // (row h-1 | row h)
    __half2 y = __floats2half2_rn(b, c);   // (row h   | row h+1)
    __half2 z = __floats2half2_rn(c, d);   // (row h+1 | row h+2)
    __half2 lo = __hmin2(x, y);
    __half2 hi = __hmax2(x, y);
    mn = __hmin2(lo, z);
    mx = __hmax2(hi, z);
    md = __hmax2(lo, __hmin2(hi, z));      // 6 HMNMX2 total
}

__device__ __forceinline__ __half2 med3h2(__half2 a, __half2 b, __half2 c) {
    __half2 mn = __hmin2(a, b);
    __half2 mx = __hmax2(a, b);
    return __hmax2(mn, __hmin2(mx, c));    // 4 HMNMX2
}

__global__ void __launch_bounds__(BLOCK)
median3x3_h2_kernel(const float* __restrict__ in, float* __restrict__ out) {
    int tid = blockIdx.x * BLOCK + threadIdx.x;
    int wc0 = (tid % TPR) * EPT;
    int pb  = tid / TPR;
    int p   = pb % PAIRS;
    int b   = pb / PAIRS;
    int h   = p * 2;                      // this thread produces rows h and h+1

    const float* img = in + (int64_t)b * IMG;
    const float* ra = img + (int64_t)max(h - 1, 0)     * ROW;  // row h-1 (clamped)
    const float* rb = img + (int64_t)h                 * ROW;  // row h
    const float* rc = img + (int64_t)(h + 1)           * ROW;  // row h+1
    const float* rd = img + (int64_t)min(h + 2, H - 1) * ROW;  // row h+2 (clamped)

    // Sorted vertical columns for window indices k=1..14 (wc = wc0-4+k)
    __half2 mn[15], md[15], mx[15];

    if (wc0 != 0 && wc0 != ROW - EPT) {
        // ---- interior: 16 x LDG.128 over window [wc0-4, wc0+12) ----
        const float4* pa = reinterpret_cast<const float4*>(ra + wc0 - 4);
        const float4* pb4 = reinterpret_cast<const float4*>(rb + wc0 - 4);
        const float4* pc = reinterpret_cast<const float4*>(rc + wc0 - 4);
        const float4* pd = reinterpret_cast<const float4*>(rd + wc0 - 4);
        #pragma unroll
        for (int j = 0; j < 4; j++) {
            float4 va = pa[j];
            float4 vb = pb4[j];
            float4 vc = pc[j];
            float4 vd = pd[j];
            float af[4] = {va.x, va.y, va.z, va.w};
            float bf[4] = {vb.x, vb.y, vb.z, vb.w};
            float cf[4] = {vc.x, vc.y, vc.z, vc.w};
            float df[4] = {vd.x, vd.y, vd.z, vd.w};
            #pragma unroll
            for (int t = 0; t < 4; t++) {
                int k = 4 * j + t;
                if (k >= 1 && k <= 14) {
                    col_sort(af[t], bf[t], cf[t], df[t], mn[k], md[k], mx[k]);
                }
            }
        }
    } else {
        // ---- edge threads: scalar loads with replicate clamp in wc space ----
        // horizontal replicate: wc<0 -> wc+3 ; wc>=ROW -> wc-3
        #pragma unroll
        for (int k = 1; k <= 14; k++) {
            int wc = wc0 - 4 + k;
            int wcs = (wc < 0) ? wc + 3 : ((wc >= ROW) ? wc - 3 : wc);
            col_sort(ra[wcs], rb[wcs], rc[wcs], rd[wcs], mn[k], md[k], mx[k]);
        }
    }

    // ---- horizontal combine: output j uses columns j+1, j+4, j+7 ----
    float r0[EPT], r1[EPT];
    #pragma unroll
    for (int j = 0; j < EPT; j++) {
        int kl = j + 1, kc = j + 4, kr = j + 7;
        __half2 lo = __hmax2(__hmax2(mn[kl], mn[kc]), mn[kr]);
        __half2 hi = __hmin2(__hmin2(mx[kl], mx[kc]), mx[kr]);
        __half2 mi = med3h2(md[kl], md[kc], md[kr]);
        __half2 m  = med3h2(lo, mi, hi);     // 12 HMNMX2 -> 2 outputs
        float2 f = __half22float2(m);
        r0[j] = f.x;   // row h
        r1[j] = f.y;   // row h+1
    }

    float* o0 = out + (int64_t)b * IMG + (int64_t)h * ROW + wc0;
    float* o1 = o0 + ROW;
    float4* po0 = reinterpret_cast<float4*>(o0);
    float4* po1 = reinterpret_cast<float4*>(o1);
    po0[0] = make_float4(r0[0], r0[1], r0[2], r0[3]);
    po0[1] = make_float4(r0[4], r0[5], r0[6], r0[7]);
    po1[0] = make_float4(r1[0], r1[1], r1[2], r1[3]);
    po1[1] = make_float4(r1[4], r1[5], r1[6], r1[7]);
}

extern "C" void kernel_launch(void* const* d_in, const int* in_sizes, int n_in,
                              void* d_out, int out_size) {
    const float* in = (const float*)d_in[0];
    float* out = (float*)d_out;
    int blocks = NTHREADS / BLOCK;   // 6144
    median3x3_h2_kernel<<<blocks, BLOCK>>>(in, out);
}

// round 3
// speedup vs baseline: 1.4913x; 1.0391x over previous
#include <cuda_runtime.h>
#include <cuda_fp16.h>
#include <cstdint>

// Input [32, 512, 512, 3] float32 NHWC, 3x3 median, replicate border.
constexpr int Bn  = 32;
constexpr int H   = 512;
constexpr int W   = 512;
constexpr int C   = 3;
constexpr int ROW = W * C;             // 1536 floats per image row
constexpr int IMG = H * ROW;
constexpr int EPT = 8;                 // wc outputs per thread per row
constexpr int TPR = ROW / EPT;         // 192
constexpr int PPT = 4;                 // row-pairs per thread (8 output rows)
constexpr int GROUPS = (H / 2) / PPT;  // 64 pair-groups per image
constexpr int NTH = Bn * GROUPS * TPR; // 393,216 threads
constexpr int BLOCK = 256;

__device__ __forceinline__ __half2 med3h2(__half2 a, __half2 b, __half2 c) {
    __half2 mn = __hmin2(a, b);
    __half2 mx = __hmax2(a, b);
    return __hmax2(mn, __hmin2(mx, c));
}
// y' = (a.high16 | b.low16)  — one PRMT
__device__ __forceinline__ __half2 prmt_h2(__half2 a, __half2 b) {
    unsigned int au = *reinterpret_cast<unsigned int*>(&a);
    unsigned int bu = *reinterpret_cast<unsigned int*>(&b);
    unsigned int r  = __byte_perm(au, bu, 0x5432);
    return *reinterpret_cast<__half2*>(&r);
}

// Load the 16-float horizontal window for one row, with replicate remap at
// the image edges done purely in registers (all loads stay vectorized).
// mode 0: interior, base = wc0-4    -> w[k] = t[k]
// mode 1: wc0==0,   base = 0        -> w[1..3]=t[0..2], w[4..15]=t[0..11]
// mode 2: wc0==ROW-8, base = ROW-16 -> w[0..11]=t[4..15], w[12..14]=t[13..15]
__device__ __forceinline__ void load_win(const float* __restrict__ r, int base,
                                         int mode, float w[16]) {
    const float4* p = reinterpret_cast<const float4*>(r + base);
    float4 t0 = p[0], t1 = p[1], t2 = p[2], t3 = p[3];
    float t[16] = {t0.x, t0.y, t0.z, t0.w, t1.x, t1.y, t1.z, t1.w,
                   t2.x, t2.y, t2.z, t2.w, t3.x, t3.y, t3.z, t3.w};
    if (mode == 0) {
        #pragma unroll
        for (int k = 0; k < 16; k++) w[k] = t[k];
    } else if (mode == 1) {
        w[0] = t[0]; w[1] = t[0]; w[2] = t[1]; w[3] = t[2];
        #pragma unroll
        for (int k = 4; k < 16; k++) w[k] = t[k - 4];
    } else {
        #pragma unroll
        for (int k = 0; k < 12; k++) w[k] = t[k + 4];
        w[12] = t[13]; w[13] = t[14]; w[14] = t[15]; w[15] = t[15];
    }
}

// Sort 14 vertical columns, combine into 8 packed medians, store 2 rows.
__device__ __forceinline__ void process_store(const __half2* x, const __half2* y,
                                              const __half2* z, float* o) {
    __half2 mn[15], md[15], mx[15];
    #pragma unroll
    for (int k = 1; k <= 14; k++) {
        __half2 lo2 = __hmin2(y[k], z[k]);
        __half2 hi2 = __hmax2(y[k], z[k]);
        mn[k] = __hmin2(x[k], lo2);
        mx[k] = __hmax2(x[k], hi2);
        md[k] = __hmax2(lo2, __hmin2(x[k], hi2));   // median via (y,z)-pair form
    }
    float r0[EPT], r1[EPT];
    #pragma unroll
    for (int j = 0; j < EPT; j++) {
        int kl = j + 1, kc = j + 4, kr = j + 7;
        __half2 lo = __hmax2(__hmax2(mn[kl], mn[kc]), mn[kr]);
        __half2 hi = __hmin2(__hmin2(mx[kl], mx[kc]), mx[kr]);
        __half2 mi = med3h2(md[kl], md[kc], md[kr]);
        __half2 m  = med3h2(lo, mi, hi);
        float2 f = __half22float2(m);
        r0[j] = f.x;
        r1[j] = f.y;
    }
    float4* po0 = reinterpret_cast<float4*>(o);
    float4* po1 = reinterpret_cast<float4*>(o + ROW);
    po0[0] = make_float4(r0[0], r0[1], r0[2], r0[3]);
    po0[1] = make_float4(r0[4], r0[5], r0[6], r0[7]);
    po1[0] = make_float4(r1[0], r1[1], r1[2], r1[3]);
    po1[1] = make_float4(r1[4], r1[5], r1[6], r1[7]);
}

__global__ void __launch_bounds__(BLOCK)
median3x3_march_kernel(const float* __restrict__ in, float* __restrict__ out) {
    int tid = blockIdx.x * BLOCK + threadIdx.x;
    int wc0  = (tid % TPR) * EPT;
    int rest = tid / TPR;
    int g    = rest % GROUPS;
    int b    = rest / GROUPS;
    int h0   = g * (2 * PPT);

    int mode = (wc0 == 0) ? 1 : ((wc0 == ROW - EPT) ? 2 : 0);
    int base = (mode == 0) ? (wc0 - 4) : ((mode == 1) ? 0 : (ROW - 16));

    const float* img = in + (int64_t)b * IMG;
    float* o = out + (int64_t)b * IMG + (int64_t)h0 * ROW + wc0;

    // ---- prologue: pair (h0, h0+1) from rows h0-1..h0+2 ----
    float wa[16], wb[16], wcf[16], wd[16];
    load_win(img + (int64_t)max(h0 - 1, 0) * ROW, base, mode, wa);
    load_win(img + (int64_t)h0 * ROW,             base, mode, wb);
    load_win(img + (int64_t)(h0 + 1) * ROW,       base, mode, wcf);
    load_win(img + (int64_t)(h0 + 2) * ROW,       base, mode, wd);

    __half2 x[15], y[15], z[15];
    #pragma unroll
    for (int k = 1; k <= 14; k++) {
        x[k] = __floats2half2_rn(wa[k], wb[k]);    // (h-1 | h)
        y[k] = __floats2half2_rn(wb[k], wcf[k]);   // (h   | h+1)
        z[k] = __floats2half2_rn(wcf[k], wd[k]);   // (h+1 | h+2)
    }
    process_store(x, y, z, o);
    o += 2 * ROW;

    // ---- march: pairs (h, h+1), h = h0+2i; reuse z as new x ----
    #pragma unroll
    for (int i = 1; i < PPT; i++) {
        int h = h0 + 2 * i;
        float w1[16], w2[16];
        load_win(img + (int64_t)(h + 1) * ROW,             base, mode, w1);
        load_win(img + (int64_t)min(h + 2, H - 1) * ROW,   base, mode, w2);
        __half2 yn[15], zn[15];
        #pragma unroll
        for (int k = 1; k <= 14; k++) {
            zn[k] = __floats2half2_rn(w1[k], w2[k]);   // (h+1 | h+2)
            yn[k] = prmt_h2(z[k], zn[k]);              // (h   | h+1)
        }
        process_store(z, yn, zn, o);
        #pragma unroll
        for (int k = 1; k <= 14; k++) z[k] = zn[k];
        o += 2 * ROW;
    }
}

extern "C" void kernel_launch(void* const* d_in, const int* in_sizes, int n_in,
                              void* d_out, int out_size) {
    const float* in = (const float*)d_in[0];
    float* out = (float*)d_out;
    int blocks = NTH / BLOCK;   // 1536
    median3x3_march_kernel<<<blocks, BLOCK>>>(in, out);
}